// round 15
// baseline (speedup 1.0000x reference)
#include <cuda_runtime.h>
#include <cuda_bf16.h>
#include <cstdint>

#define H 2048
#define E 64
#define MAXN 16384
#define TILE_M 128
#define KC 64
#define CHUNKS (H / KC)  // 32
#define MAXFLAG 512

// ---------------- device scratch ----------------
__device__ __align__(16) __nv_bfloat16 g_Wh[E * H];
__device__ __align__(16) __nv_bfloat16 g_Wl[E * H];
__device__ float g_partial[(MAXN / TILE_M) * E];
__device__ int   g_cnt[E];
__device__ int   g_nflag;
__device__ int   g_flaglist[MAXFLAG];

// ---------------- helpers ----------------
__device__ __forceinline__ uint32_t smem_u32(const void* p) {
    uint32_t a;
    asm("{ .reg .u64 t; cvta.to.shared.u64 t, %1; cvt.u32.u64 %0, t; }" : "=r"(a) : "l"(p));
    return a;
}
__device__ __forceinline__ uint32_t sw128(uint32_t o) { return o ^ ((o >> 3) & 0x70); }

__device__ __forceinline__ void split2(float v, float& h, float& l) {
    h = __bfloat162float(__float2bfloat16_rn(v));
    l = v - h;
}
__device__ __forceinline__ uint32_t packbf(float a, float b) {
    __nv_bfloat162 t = __floats2bfloat162_rn(a, b);
    return *reinterpret_cast<uint32_t*>(&t);
}

#define CP_ASYNC16(dst, src)                                                             \
    asm volatile("cp.async.cg.shared.global [%0], [%1], 16;" :: "r"(dst), "l"(src))
#define CP_COMMIT()  asm volatile("cp.async.commit_group;" ::: "memory")
#define CP_WAIT2()   asm volatile("cp.async.wait_group 2;" ::: "memory")
#define CP_WAIT0()   asm volatile("cp.async.wait_group 0;" ::: "memory")

#define LDSM4(r, addr)                                                                   \
    asm volatile("ldmatrix.sync.aligned.m8n8.x4.shared.b16 {%0,%1,%2,%3}, [%4];"         \
        : "=r"((r)[0]), "=r"((r)[1]), "=r"((r)[2]), "=r"((r)[3]) : "r"(addr))

#define MMA16816(ac, a, b0, b1)                                                          \
    asm volatile("mma.sync.aligned.m16n8k16.row.col.f32.bf16.bf16.f32 "                  \
        "{%0,%1,%2,%3}, {%4,%5,%6,%7}, {%8,%9}, {%0,%1,%2,%3};"                          \
        : "+f"((ac)[0]), "+f"((ac)[1]), "+f"((ac)[2]), "+f"((ac)[3])                     \
        : "r"((a)[0]), "r"((a)[1]), "r"((a)[2]), "r"((a)[3]), "r"(b0), "r"(b1))

// ---------------- kernel 0: split W once, zero counters ----------------
__global__ __launch_bounds__(256) void prep_kernel(const float* __restrict__ W) {
    const int i = (blockIdx.x * 256 + threadIdx.x) * 8;
    if (i < E * H) {
        float4 v0 = *(const float4*)(W + i);
        float4 v1 = *(const float4*)(W + i + 4);
        float vv[8] = {v0.x, v0.y, v0.z, v0.w, v1.x, v1.y, v1.z, v1.w};
        uint32_t ph[4], pl[4];
#pragma unroll
        for (int q = 0; q < 4; q++) {
            float h0, l0, h1, l1;
            split2(vv[2 * q], h0, l0);
            split2(vv[2 * q + 1], h1, l1);
            ph[q] = packbf(h0, h1);
            pl[q] = packbf(l0, l1);
        }
        *(uint4*)(g_Wh + i) = make_uint4(ph[0], ph[1], ph[2], ph[3]);
        *(uint4*)(g_Wl + i) = make_uint4(pl[0], pl[1], pl[2], pl[3]);
    }
    if (blockIdx.x == 0 && threadIdx.x < E) g_cnt[threadIdx.x] = 0;
    if (blockIdx.x == 0 && threadIdx.x == 0) g_nflag = 0;
}

// ---------------- kernel 1: in-gemm split + 4-stage B cp.async + HMMA ----------------
// A: 2 buffers x (A_hi 16KB + A_lo 16KB) = 64KB at offset 0
// B: 4 stages x (B_hi 8KB + B_lo 8KB) = 64KB at offset 65536
static constexpr int A_SZ    = 16384;
static constexpr int ABUF_SZ = 2 * A_SZ;           // 32768
static constexpr int OFF_B   = 2 * ABUF_SZ;        // 65536
static constexpr int B_SZ    = 8192;
static constexpr int BSTG_SZ = 2 * B_SZ;           // 16384
static constexpr int OFF_SP  = OFF_B + 4 * BSTG_SZ;  // 131072
static constexpr int SMEM_TOTAL = OFF_SP + 4 * E * 4;  // 132096

__global__ __launch_bounds__(256, 1) void gemm_kernel(const float* __restrict__ x,
                                                      float* __restrict__ out, int N) {
    extern __shared__ char sdata[];
    const uint32_t sb = smem_u32(sdata);
    const int tid = threadIdx.x;
    const int wid = tid >> 5, lid = tid & 31;
    const int row0 = blockIdx.x * TILE_M;

    // A loader map: 2 threads/row
    const int rA = tid >> 1;        // 0..127
    const int kA = (tid & 1) * 32;  // element offset within chunk

    // ldmatrix lane maps
    const int idx = lid >> 3;
    const int a_row = wid * 16 + (idx & 1) * 8 + (lid & 7);
    const uint32_t a_rowbyte = (uint32_t)a_row * 128;
    const uint32_t a_xor = (uint32_t)(a_row & 7) << 4;
    const uint32_t a_k2 = (uint32_t)(idx >> 1) * 16;
    const int b_n0 = (idx >> 1) * 8 + (lid & 7);
    const uint32_t b_k2 = (uint32_t)(idx & 1) * 16;
    uint32_t b_rowbyte[4], b_xor[4];
#pragma unroll
    for (int j = 0; j < 4; j++) {
        int nr = j * 16 + b_n0;
        b_rowbyte[j] = (uint32_t)nr * 128;
        b_xor[j] = (uint32_t)(nr & 7) << 4;
    }

    float acc[8][4] = {};
    float4 a_raw[8];

    const float* xrow = x + (size_t)(row0 + rA) * H + kA;
    const uint32_t a_sts = sw128((uint32_t)(rA * 128 + kA * 2));  // base; +j*16 swizzle-safe? no — compute per j

    // ---- prologue ----
    // B stages 0..2 via cp.async (one commit each)
#pragma unroll
    for (int s = 0; s < 3; s++) {
        const uint32_t stg = sb + OFF_B + s * BSTG_SZ;
#pragma unroll
        for (int q = 0; q < 2; q++) {
            const int u = q * 256 + tid;
            const int r = u >> 3, cc = u & 7;
            const uint32_t dst = sw128((uint32_t)(r * 128 + cc * 16));
            const size_t srcoff = (size_t)r * H + s * KC + cc * 8;
            CP_ASYNC16(stg + dst, g_Wh + srcoff);
            CP_ASYNC16(stg + B_SZ + dst, g_Wl + srcoff);
        }
        CP_COMMIT();
    }
    // A chunk 0: LDG + split + STS -> abuf0
    {
#pragma unroll
        for (int j = 0; j < 8; j++) a_raw[j] = ((const float4*)xrow)[j];
#pragma unroll
        for (int j = 0; j < 4; j++) {
            float v[8] = {a_raw[2 * j].x, a_raw[2 * j].y, a_raw[2 * j].z, a_raw[2 * j].w,
                          a_raw[2 * j + 1].x, a_raw[2 * j + 1].y, a_raw[2 * j + 1].z, a_raw[2 * j + 1].w};
            uint32_t ph[4], pl[4];
#pragma unroll
            for (int q = 0; q < 4; q++) {
                float h0, l0, h1, l1;
                split2(v[2 * q], h0, l0);
                split2(v[2 * q + 1], h1, l1);
                ph[q] = packbf(h0, h1); pl[q] = packbf(l0, l1);
            }
            uint32_t off = sw128((uint32_t)(rA * 128 + kA * 2 + j * 16));
            *(uint4*)(sdata + off)        = make_uint4(ph[0], ph[1], ph[2], ph[3]);
            *(uint4*)(sdata + A_SZ + off) = make_uint4(pl[0], pl[1], pl[2], pl[3]);
        }
    }
    CP_WAIT2();        // B stage 0 retired
    __syncthreads();

    for (int c = 0; c < CHUNKS; c++) {
        // ---- issue B stage c+3 ----
        if (c + 3 < CHUNKS) {
            const uint32_t stg = sb + OFF_B + ((c + 3) & 3) * BSTG_SZ;
            const int k0 = (c + 3) * KC;
#pragma unroll
            for (int q = 0; q < 2; q++) {
                const int u = q * 256 + tid;
                const int r = u >> 3, cc = u & 7;
                const uint32_t dst = sw128((uint32_t)(r * 128 + cc * 16));
                const size_t srcoff = (size_t)r * H + k0 + cc * 8;
                CP_ASYNC16(stg + dst, g_Wh + srcoff);
                CP_ASYNC16(stg + B_SZ + dst, g_Wl + srcoff);
            }
        }
        CP_COMMIT();

        // ---- LDG A chunk c+1 (latency hidden by MMA section) ----
        const bool more = (c + 1 < CHUNKS);
        if (more) {
            const float* xp = xrow + (c + 1) * KC;
#pragma unroll
            for (int j = 0; j < 8; j++) a_raw[j] = ((const float4*)xp)[j];
        }

        // ---- MMA on chunk c ----
        const uint32_t abuf_u = sb + (c & 1) * ABUF_SZ;
        const uint32_t bstg   = sb + OFF_B + (c & 3) * BSTG_SZ;
#pragma unroll
        for (int ks = 0; ks < 4; ks++) {
            const uint32_t kcol = (uint32_t)ks * 32;
            uint32_t Af[2][4], Bh[4][4], Bl[4][4];
            LDSM4(Af[0], abuf_u + a_rowbyte + ((kcol + a_k2) ^ a_xor));
            LDSM4(Af[1], abuf_u + A_SZ + a_rowbyte + ((kcol + a_k2) ^ a_xor));
#pragma unroll
            for (int j = 0; j < 4; j++)
                LDSM4(Bh[j], bstg + b_rowbyte[j] + ((kcol + b_k2) ^ b_xor[j]));
#pragma unroll
            for (int j = 0; j < 4; j++) {
                MMA16816(acc[2 * j],     Af[0], Bh[j][0], Bh[j][1]);
                MMA16816(acc[2 * j + 1], Af[0], Bh[j][2], Bh[j][3]);
            }
#pragma unroll
            for (int j = 0; j < 4; j++)
                LDSM4(Bl[j], bstg + B_SZ + b_rowbyte[j] + ((kcol + b_k2) ^ b_xor[j]));
#pragma unroll
            for (int j = 0; j < 4; j++) {
                MMA16816(acc[2 * j],     Af[1], Bh[j][0], Bh[j][1]);
                MMA16816(acc[2 * j + 1], Af[1], Bh[j][2], Bh[j][3]);
            }
#pragma unroll
            for (int j = 0; j < 4; j++) {
                MMA16816(acc[2 * j],     Af[0], Bl[j][0], Bl[j][1]);
                MMA16816(acc[2 * j + 1], Af[0], Bl[j][2], Bl[j][3]);
            }
        }

        // ---- split + STS A chunk c+1 into abuf (c+1)&1 ----
        if (more) {
            char* abuf = sdata + ((c + 1) & 1) * ABUF_SZ;
#pragma unroll
            for (int j = 0; j < 4; j++) {
                float v[8] = {a_raw[2 * j].x, a_raw[2 * j].y, a_raw[2 * j].z, a_raw[2 * j].w,
                              a_raw[2 * j + 1].x, a_raw[2 * j + 1].y, a_raw[2 * j + 1].z, a_raw[2 * j + 1].w};
                uint32_t ph[4], pl[4];
#pragma unroll
                for (int q = 0; q < 4; q++) {
                    float h0, l0, h1, l1;
                    split2(v[2 * q], h0, l0);
                    split2(v[2 * q + 1], h1, l1);
                    ph[q] = packbf(h0, h1); pl[q] = packbf(l0, l1);
                }
                uint32_t off = sw128((uint32_t)(rA * 128 + kA * 2 + j * 16));
                *(uint4*)(abuf + off)        = make_uint4(ph[0], ph[1], ph[2], ph[3]);
                *(uint4*)(abuf + A_SZ + off) = make_uint4(pl[0], pl[1], pl[2], pl[3]);
            }
        }
        CP_WAIT2();       // B stage c+1 retired
        __syncthreads();  // STS(c+1) + B(c+1) visible to all
    }

    // ---- C frags -> smem logits (overlay A buffers) ----
    float* lg = (float*)sdata;
    {
        const int r0f = wid * 16 + (lid >> 2);
        const int c0f = (lid & 3) * 2;
#pragma unroll
        for (int nt = 0; nt < 8; nt++) {
            int col = nt * 8 + c0f;
            lg[r0f * 65 + col]           = acc[nt][0];
            lg[r0f * 65 + col + 1]       = acc[nt][1];
            lg[(r0f + 8) * 65 + col]     = acc[nt][2];
            lg[(r0f + 8) * 65 + col + 1] = acc[nt][3];
        }
    }
    __syncthreads();

    // ---- per-token softmax / top-2 / near-tie flag / reductions ----
    float* s_part = (float*)(sdata + OFF_SP);  // [4][64]
    if (tid < 128) {
        float p[E];
#pragma unroll
        for (int e = 0; e < E; e++) p[e] = lg[tid * 65 + e];

        float mx = p[0];
#pragma unroll
        for (int e = 1; e < E; e++) mx = fmaxf(mx, p[e]);
        float denom = 0.f;
#pragma unroll
        for (int e = 0; e < E; e++) { p[e] = __expf(p[e] - mx); denom += p[e]; }
        const float inv = 1.f / denom;
#pragma unroll
        for (int e = 0; e < E; e++) p[e] *= inv;

        float m1 = -1.f, m2 = -1.f, m3 = -1.f;
        int i1 = 0, i2 = 0;
#pragma unroll
        for (int e = 0; e < E; e++) {
            float v = p[e];
            if (v > m1)      { m3 = m2; m2 = m1; i2 = i1; m1 = v; i1 = e; }
            else if (v > m2) { m3 = m2; m2 = v; i2 = e; }
            else if (v > m3) { m3 = v; }
        }
        const int token = row0 + tid;
        const float d = m1 + m2 + 1e-6f;
        out[(size_t)token * 2 + 0] = m1 / d;
        out[(size_t)token * 2 + 1] = m2 / d;
        float* oidx = out + (size_t)2 * N;
        oidx[(size_t)token * 2 + 0] = (float)i1;
        oidx[(size_t)token * 2 + 1] = (float)i2;

        atomicAdd(&g_cnt[i1], 1);
        atomicAdd(&g_cnt[i2], 1);

        if ((m1 - m2 < 6e-5f * m1) || (m2 - m3 < 6e-5f * m2)) {
            int s = atomicAdd(&g_nflag, 1);
            if (s < MAXFLAG) g_flaglist[s] = token;
        }

#pragma unroll
        for (int e = 0; e < E; e++) {
            float v = p[e];
            v += __shfl_xor_sync(0xffffffffu, v, 16);
            v += __shfl_xor_sync(0xffffffffu, v, 8);
            v += __shfl_xor_sync(0xffffffffu, v, 4);
            v += __shfl_xor_sync(0xffffffffu, v, 2);
            v += __shfl_xor_sync(0xffffffffu, v, 1);
            if (lid == 0) s_part[wid * E + e] = v;
        }
    }
    __syncthreads();
    if (tid < E) {
        float s = s_part[tid] + s_part[E + tid] + s_part[2 * E + tid] + s_part[3 * E + tid];
        g_partial[blockIdx.x * E + tid] = s;
    }
}

// ---------------- kernel 2: exact fp32 fixup (1 block per flagged token) ----------------
__global__ __launch_bounds__(256) void fixup_kernel(const float* __restrict__ x,
                                                    const float* __restrict__ W,
                                                    float* __restrict__ out, int N) {
    int n = g_nflag;
    if (n > MAXFLAG) n = MAXFLAG;
    if (blockIdx.x >= n) return;
    const int token = g_flaglist[blockIdx.x];

    __shared__ float sq[4][E];
    __shared__ float sl[E];
    const int e = threadIdx.x & 63;
    const int q = threadIdx.x >> 6;

    const float* xr = x + (size_t)token * H + q * (H / 4);
    const float* wr = W + (size_t)e * H + q * (H / 4);
    float a = 0.f;
#pragma unroll 4
    for (int h = 0; h < H / 4; h += 4) {
        float4 xv = *(const float4*)(xr + h);
        float4 wv = *(const float4*)(wr + h);
        a += xv.x * wv.x + xv.y * wv.y + xv.z * wv.z + xv.w * wv.w;
    }
    sq[q][e] = a;
    __syncthreads();
    if (threadIdx.x < E) sl[threadIdx.x] = sq[0][threadIdx.x] + sq[1][threadIdx.x]
                                         + sq[2][threadIdx.x] + sq[3][threadIdx.x];
    __syncthreads();
    if (threadIdx.x == 0) {
        float mx = sl[0];
        for (int i = 1; i < E; i++) mx = fmaxf(mx, sl[i]);
        float Z = 0.f;
        for (int i = 0; i < E; i++) Z += __expf(sl[i] - mx);
        float m1 = -1e30f, m2 = -1e30f;
        int i1 = 0, i2 = 0;
        for (int i = 0; i < E; i++) {
            float v = sl[i];
            if (v > m1)      { m2 = m1; i2 = i1; m1 = v; i1 = i; }
            else if (v > m2) { m2 = v; i2 = i; }
        }
        float p1 = __expf(m1 - mx) / Z;
        float p2 = __expf(m2 - mx) / Z;
        float d = p1 + p2 + 1e-6f;
        float* oidx = out + (size_t)2 * N;
        int o1 = (int)oidx[(size_t)token * 2 + 0];
        int o2 = (int)oidx[(size_t)token * 2 + 1];
        out[(size_t)token * 2 + 0] = p1 / d;
        out[(size_t)token * 2 + 1] = p2 / d;
        oidx[(size_t)token * 2 + 0] = (float)i1;
        oidx[(size_t)token * 2 + 1] = (float)i2;
        atomicAdd(&g_cnt[o1], -1);
        atomicAdd(&g_cnt[o2], -1);
        atomicAdd(&g_cnt[i1], 1);
        atomicAdd(&g_cnt[i2], 1);
    }
}

// ---------------- kernel 3: aux loss + counts ----------------
__global__ __launch_bounds__(512) void finalize_kernel(float* __restrict__ out, int N) {
    __shared__ float red[8][E];
    __shared__ float s2[2];
    const int e = threadIdx.x & 63;
    const int part = threadIdx.x >> 6;
    const int nb = N / TILE_M;
    float s = 0.f;
    for (int bb = part; bb < nb; bb += 8) s += g_partial[bb * E + e];
    red[part][e] = s;
    __syncthreads();
    float val = 0.f;
    if (threadIdx.x < E) {
        s = 0.f;
#pragma unroll
        for (int r = 0; r < 8; r++) s += red[r][e];
        const float pm  = s / (float)N;
        const float cnt = (float)g_cnt[e];
        const float am  = cnt / (float)N;
        out[(size_t)4 * N + 1 + e] = cnt;
        val = pm * pm + am * am;
    }
    val += __shfl_xor_sync(0xffffffffu, val, 16);
    val += __shfl_xor_sync(0xffffffffu, val, 8);
    val += __shfl_xor_sync(0xffffffffu, val, 4);
    val += __shfl_xor_sync(0xffffffffu, val, 2);
    val += __shfl_xor_sync(0xffffffffu, val, 1);
    if ((threadIdx.x & 31) == 0 && threadIdx.x < 64) s2[threadIdx.x >> 5] = val;
    __syncthreads();
    if (threadIdx.x == 0) out[(size_t)4 * N] = (float)E * (s2[0] + s2[1]);
}

extern "C" void kernel_launch(void* const* d_in, const int* in_sizes, int n_in,
                              void* d_out, int out_size) {
    const float* x = (const float*)d_in[0];
    const float* W = (const float*)d_in[1];
    float* out = (float*)d_out;
    const int N = in_sizes[0] / H;  // 16384

    cudaFuncSetAttribute(gemm_kernel, cudaFuncAttributeMaxDynamicSharedMemorySize,
                         SMEM_TOTAL);

    prep_kernel<<<(E * H) / 2048, 256>>>(W);
    gemm_kernel<<<N / TILE_M, 256, SMEM_TOTAL>>>(x, out, N);
    fixup_kernel<<<MAXFLAG, 256>>>(x, W, out, N);
    finalize_kernel<<<1, 512>>>(out, N);
}

// round 16
// speedup vs baseline: 1.0711x; 1.0711x over previous
#include <cuda_runtime.h>
#include <cuda_bf16.h>
#include <cstdint>

#define H 2048
#define E 64
#define MAXN 16384
#define TILE_M 128
#define KC 64
#define CHUNKS (H / KC)  // 32
#define MAXFLAG 512
#define NTHREADS 384     // 256 consumer + 128 producer

// ---------------- device scratch ----------------
__device__ __align__(16) __nv_bfloat16 g_Wh[E * H];
__device__ __align__(16) __nv_bfloat16 g_Wl[E * H];
__device__ float g_partial[(MAXN / TILE_M) * E];
__device__ int   g_cnt[E];
__device__ int   g_nflag;
__device__ int   g_flaglist[MAXFLAG];

// ---------------- helpers ----------------
__device__ __forceinline__ uint32_t smem_u32(const void* p) {
    uint32_t a;
    asm("{ .reg .u64 t; cvta.to.shared.u64 t, %1; cvt.u32.u64 %0, t; }" : "=r"(a) : "l"(p));
    return a;
}
__device__ __forceinline__ uint32_t sw128(uint32_t o) { return o ^ ((o >> 3) & 0x70); }

__device__ __forceinline__ void split2(float v, float& h, float& l) {
    h = __bfloat162float(__float2bfloat16_rn(v));
    l = v - h;
}
__device__ __forceinline__ uint32_t packbf(float a, float b) {
    __nv_bfloat162 t = __floats2bfloat162_rn(a, b);
    return *reinterpret_cast<uint32_t*>(&t);
}

#define CP_ASYNC16(dst, src)                                                             \
    asm volatile("cp.async.cg.shared.global [%0], [%1], 16;" :: "r"(dst), "l"(src))
#define CP_COMMIT()  asm volatile("cp.async.commit_group;" ::: "memory")
#define CP_WAIT0()   asm volatile("cp.async.wait_group 0;" ::: "memory")

#define BAR_SYNC(id)   asm volatile("bar.sync %0, %1;" :: "r"(id), "r"(NTHREADS) : "memory")
#define BAR_ARRIVE(id) asm volatile("bar.arrive %0, %1;" :: "r"(id), "r"(NTHREADS) : "memory")

#define LDSM4(r, addr)                                                                   \
    asm volatile("ldmatrix.sync.aligned.m8n8.x4.shared.b16 {%0,%1,%2,%3}, [%4];"         \
        : "=r"((r)[0]), "=r"((r)[1]), "=r"((r)[2]), "=r"((r)[3]) : "r"(addr))

#define MMA16816(ac, a, b0, b1)                                                          \
    asm volatile("mma.sync.aligned.m16n8k16.row.col.f32.bf16.bf16.f32 "                  \
        "{%0,%1,%2,%3}, {%4,%5,%6,%7}, {%8,%9}, {%0,%1,%2,%3};"                          \
        : "+f"((ac)[0]), "+f"((ac)[1]), "+f"((ac)[2]), "+f"((ac)[3])                     \
        : "r"((a)[0]), "r"((a)[1]), "r"((a)[2]), "r"((a)[3]), "r"(b0), "r"(b1))

// ---------------- kernel 0: split W once, zero counters ----------------
__global__ __launch_bounds__(256) void prep_kernel(const float* __restrict__ W) {
    const int i = (blockIdx.x * 256 + threadIdx.x) * 8;
    if (i < E * H) {
        float4 v0 = *(const float4*)(W + i);
        float4 v1 = *(const float4*)(W + i + 4);
        float vv[8] = {v0.x, v0.y, v0.z, v0.w, v1.x, v1.y, v1.z, v1.w};
        uint32_t ph[4], pl[4];
#pragma unroll
        for (int q = 0; q < 4; q++) {
            float h0, l0, h1, l1;
            split2(vv[2 * q], h0, l0);
            split2(vv[2 * q + 1], h1, l1);
            ph[q] = packbf(h0, h1);
            pl[q] = packbf(l0, l1);
        }
        *(uint4*)(g_Wh + i) = make_uint4(ph[0], ph[1], ph[2], ph[3]);
        *(uint4*)(g_Wl + i) = make_uint4(pl[0], pl[1], pl[2], pl[3]);
    }
    if (blockIdx.x == 0 && threadIdx.x < E) g_cnt[threadIdx.x] = 0;
    if (blockIdx.x == 0 && threadIdx.x == 0) g_nflag = 0;
}

// ---------------- kernel 1: warp-specialized split-bf16 HMMA GEMM ----------------
// Stage (48KB): A_hi@0 (16K) A_lo@16K B_hi@32K B_lo@40K. Depth 2 -> 96KB.
static constexpr int A_SZ   = 16384;
static constexpr int B_SZ   = 8192;
static constexpr int B_OFFS = 2 * A_SZ;             // 32768
static constexpr int STG_SZ = B_OFFS + 2 * B_SZ;    // 49152
static constexpr int OFF_SP = 2 * STG_SZ;           // 98304
static constexpr int SMEM_TOTAL = OFF_SP + 4 * E * 4;  // 99328

// named barriers: ready[s] = 1+s, free[s] = 3+s  (s in {0,1})
__global__ __launch_bounds__(NTHREADS, 1) void gemm_kernel(const float* __restrict__ x,
                                                           float* __restrict__ out, int N) {
    extern __shared__ char sdata[];
    const uint32_t sb = smem_u32(sdata);
    const int tid = threadIdx.x;
    const int wid = tid >> 5, lid = tid & 31;
    const int row0 = blockIdx.x * TILE_M;

    if (tid >= 256) {
        // ================= PRODUCER (warps 8-11, 128 threads) =================
        const int tp = tid - 256;           // 0..127
        const int rB = tp >> 1;             // 0..63
        const int cB = (tp & 1) * 4;        // 16B-unit offset within row
        const float* xrow = x + (size_t)(row0 + tp) * H;  // one token row per thread
        const uint32_t a_base = (uint32_t)tp * 128;
        const size_t wrow = (size_t)rB * H;

        for (int c = 0; c < CHUNKS; c++) {
            const int s = c & 1;
            if (c >= 2) BAR_SYNC(3 + s);    // wait consumers done with stage s
            const uint32_t stg = sb + s * STG_SZ;
            const int k0 = c * KC;

            // B tiles via cp.async
#pragma unroll
            for (int q = 0; q < 4; q++) {
                const uint32_t dst = sw128((uint32_t)(rB * 128 + (cB + q) * 16));
                const size_t srcoff = wrow + k0 + (cB + q) * 8;
                CP_ASYNC16(stg + B_OFFS + dst, g_Wh + srcoff);
                CP_ASYNC16(stg + B_OFFS + B_SZ + dst, g_Wl + srcoff);
            }
            CP_COMMIT();

            // A row: LDG 64 fp32, split, STS
            float4 a_raw[16];
            const float4* xp = (const float4*)(xrow + k0);
#pragma unroll
            for (int j = 0; j < 16; j++) a_raw[j] = xp[j];
            char* stgp = sdata + s * STG_SZ;
#pragma unroll
            for (int j = 0; j < 8; j++) {
                float v[8] = {a_raw[2 * j].x, a_raw[2 * j].y, a_raw[2 * j].z, a_raw[2 * j].w,
                              a_raw[2 * j + 1].x, a_raw[2 * j + 1].y, a_raw[2 * j + 1].z, a_raw[2 * j + 1].w};
                uint32_t ph[4], pl[4];
#pragma unroll
                for (int q = 0; q < 4; q++) {
                    float h0, l0, h1, l1;
                    split2(v[2 * q], h0, l0);
                    split2(v[2 * q + 1], h1, l1);
                    ph[q] = packbf(h0, h1); pl[q] = packbf(l0, l1);
                }
                const uint32_t off = sw128(a_base + j * 16);
                *(uint4*)(stgp + off)        = make_uint4(ph[0], ph[1], ph[2], ph[3]);
                *(uint4*)(stgp + A_SZ + off) = make_uint4(pl[0], pl[1], pl[2], pl[3]);
            }
            CP_WAIT0();                      // B landed (producer-issued)
            BAR_ARRIVE(1 + s);               // stage s ready
        }
    } else {
        // ================= CONSUMER (warps 0-7, 256 threads) =================
        const int idx = lid >> 3;
        const int a_row = wid * 16 + (idx & 1) * 8 + (lid & 7);
        const uint32_t a_rowbyte = (uint32_t)a_row * 128;
        const uint32_t a_xor = (uint32_t)(a_row & 7) << 4;
        const uint32_t a_k2 = (uint32_t)(idx >> 1) * 16;
        const int b_n0 = (idx >> 1) * 8 + (lid & 7);
        const uint32_t b_k2 = (uint32_t)(idx & 1) * 16;
        uint32_t b_rowbyte[4], b_xor[4];
#pragma unroll
        for (int j = 0; j < 4; j++) {
            int nr = j * 16 + b_n0;
            b_rowbyte[j] = (uint32_t)nr * 128;
            b_xor[j] = (uint32_t)(nr & 7) << 4;
        }

        float acc[8][4] = {};

        for (int c = 0; c < CHUNKS; c++) {
            const int s = c & 1;
            BAR_SYNC(1 + s);                 // wait stage s ready
            const uint32_t sbuf = sb + s * STG_SZ;
#pragma unroll
            for (int ks = 0; ks < 4; ks++) {
                const uint32_t kcol = (uint32_t)ks * 32;
                uint32_t Af[2][4], Bh[4][4], Bl[4][4];
                LDSM4(Af[0], sbuf + a_rowbyte + ((kcol + a_k2) ^ a_xor));
                LDSM4(Af[1], sbuf + A_SZ + a_rowbyte + ((kcol + a_k2) ^ a_xor));
#pragma unroll
                for (int j = 0; j < 4; j++)
                    LDSM4(Bh[j], sbuf + B_OFFS + b_rowbyte[j] + ((kcol + b_k2) ^ b_xor[j]));
#pragma unroll
                for (int j = 0; j < 4; j++) {
                    MMA16816(acc[2 * j],     Af[0], Bh[j][0], Bh[j][1]);
                    MMA16816(acc[2 * j + 1], Af[0], Bh[j][2], Bh[j][3]);
                }
#pragma unroll
                for (int j = 0; j < 4; j++)
                    LDSM4(Bl[j], sbuf + B_OFFS + B_SZ + b_rowbyte[j] + ((kcol + b_k2) ^ b_xor[j]));
#pragma unroll
                for (int j = 0; j < 4; j++) {
                    MMA16816(acc[2 * j],     Af[1], Bh[j][0], Bh[j][1]);
                    MMA16816(acc[2 * j + 1], Af[1], Bh[j][2], Bh[j][3]);
                }
#pragma unroll
                for (int j = 0; j < 4; j++) {
                    MMA16816(acc[2 * j],     Af[0], Bl[j][0], Bl[j][1]);
                    MMA16816(acc[2 * j + 1], Af[0], Bl[j][2], Bl[j][3]);
                }
            }
            BAR_ARRIVE(3 + s);               // stage s free
        }

        // stash acc -> smem logits happens after the全-thread barrier below
        // (store here into registers; write after __syncthreads)
        // We fall through; logits write is below, guarded by tid<256.
        __syncthreads();                     // join producers (they're done)
        float* lg = (float*)sdata;
        {
            const int r0f = wid * 16 + (lid >> 2);
            const int c0f = (lid & 3) * 2;
#pragma unroll
            for (int nt = 0; nt < 8; nt++) {
                int col = nt * 8 + c0f;
                lg[r0f * 65 + col]           = acc[nt][0];
                lg[r0f * 65 + col + 1]       = acc[nt][1];
                lg[(r0f + 8) * 65 + col]     = acc[nt][2];
                lg[(r0f + 8) * 65 + col + 1] = acc[nt][3];
            }
        }
        goto epilogue_sync;
    }
    // producers join here
    __syncthreads();
epilogue_sync:
    __syncthreads();

    // ---- per-token softmax / top-2 / near-tie flag / reductions ----
    {
        float* lg = (float*)sdata;
        float* s_part = (float*)(sdata + OFF_SP);  // [4][64]
        if (tid < 128) {
            float p[E];
#pragma unroll
            for (int e = 0; e < E; e++) p[e] = lg[tid * 65 + e];

            float mx = p[0];
#pragma unroll
            for (int e = 1; e < E; e++) mx = fmaxf(mx, p[e]);
            float denom = 0.f;
#pragma unroll
            for (int e = 0; e < E; e++) { p[e] = __expf(p[e] - mx); denom += p[e]; }
            const float inv = 1.f / denom;
#pragma unroll
            for (int e = 0; e < E; e++) p[e] *= inv;

            float m1 = -1.f, m2 = -1.f, m3 = -1.f;
            int i1 = 0, i2 = 0;
#pragma unroll
            for (int e = 0; e < E; e++) {
                float v = p[e];
                if (v > m1)      { m3 = m2; m2 = m1; i2 = i1; m1 = v; i1 = e; }
                else if (v > m2) { m3 = m2; m2 = v; i2 = e; }
                else if (v > m3) { m3 = v; }
            }
            const int token = row0 + tid;
            const float d = m1 + m2 + 1e-6f;
            out[(size_t)token * 2 + 0] = m1 / d;
            out[(size_t)token * 2 + 1] = m2 / d;
            float* oidx = out + (size_t)2 * N;
            oidx[(size_t)token * 2 + 0] = (float)i1;
            oidx[(size_t)token * 2 + 1] = (float)i2;

            atomicAdd(&g_cnt[i1], 1);
            atomicAdd(&g_cnt[i2], 1);

            if ((m1 - m2 < 6e-5f * m1) || (m2 - m3 < 6e-5f * m2)) {
                int s = atomicAdd(&g_nflag, 1);
                if (s < MAXFLAG) g_flaglist[s] = token;
            }

#pragma unroll
            for (int e = 0; e < E; e++) {
                float v = p[e];
                v += __shfl_xor_sync(0xffffffffu, v, 16);
                v += __shfl_xor_sync(0xffffffffu, v, 8);
                v += __shfl_xor_sync(0xffffffffu, v, 4);
                v += __shfl_xor_sync(0xffffffffu, v, 2);
                v += __shfl_xor_sync(0xffffffffu, v, 1);
                if (lid == 0) s_part[wid * E + e] = v;
            }
        }
        __syncthreads();
        if (tid < E) {
            float s = s_part[tid] + s_part[E + tid] + s_part[2 * E + tid] + s_part[3 * E + tid];
            g_partial[blockIdx.x * E + tid] = s;
        }
    }
}

// ---------------- kernel 2: exact fp32 fixup (1 block per flagged token) ----------------
__global__ __launch_bounds__(256) void fixup_kernel(const float* __restrict__ x,
                                                    const float* __restrict__ W,
                                                    float* __restrict__ out, int N) {
    int n = g_nflag;
    if (n > MAXFLAG) n = MAXFLAG;
    if (blockIdx.x >= n) return;
    const int token = g_flaglist[blockIdx.x];

    __shared__ float sq[4][E];
    __shared__ float sl[E];
    const int e = threadIdx.x & 63;
    const int q = threadIdx.x >> 6;

    const float* xr = x + (size_t)token * H + q * (H / 4);
    const float* wr = W + (size_t)e * H + q * (H / 4);
    float a = 0.f;
#pragma unroll 4
    for (int h = 0; h < H / 4; h += 4) {
        float4 xv = *(const float4*)(xr + h);
        float4 wv = *(const float4*)(wr + h);
        a += xv.x * wv.x + xv.y * wv.y + xv.z * wv.z + xv.w * wv.w;
    }
    sq[q][e] = a;
    __syncthreads();
    if (threadIdx.x < E) sl[threadIdx.x] = sq[0][threadIdx.x] + sq[1][threadIdx.x]
                                         + sq[2][threadIdx.x] + sq[3][threadIdx.x];
    __syncthreads();
    if (threadIdx.x == 0) {
        float mx = sl[0];
        for (int i = 1; i < E; i++) mx = fmaxf(mx, sl[i]);
        float Z = 0.f;
        for (int i = 0; i < E; i++) Z += __expf(sl[i] - mx);
        float m1 = -1e30f, m2 = -1e30f;
        int i1 = 0, i2 = 0;
        for (int i = 0; i < E; i++) {
            float v = sl[i];
            if (v > m1)      { m2 = m1; i2 = i1; m1 = v; i1 = i; }
            else if (v > m2) { m2 = v; i2 = i; }
        }
        float p1 = __expf(m1 - mx) / Z;
        float p2 = __expf(m2 - mx) / Z;
        float d = p1 + p2 + 1e-6f;
        float* oidx = out + (size_t)2 * N;
        int o1 = (int)oidx[(size_t)token * 2 + 0];
        int o2 = (int)oidx[(size_t)token * 2 + 1];
        out[(size_t)token * 2 + 0] = p1 / d;
        out[(size_t)token * 2 + 1] = p2 / d;
        oidx[(size_t)token * 2 + 0] = (float)i1;
        oidx[(size_t)token * 2 + 1] = (float)i2;
        atomicAdd(&g_cnt[o1], -1);
        atomicAdd(&g_cnt[o2], -1);
        atomicAdd(&g_cnt[i1], 1);
        atomicAdd(&g_cnt[i2], 1);
    }
}

// ---------------- kernel 3: aux loss + counts ----------------
__global__ __launch_bounds__(512) void finalize_kernel(float* __restrict__ out, int N) {
    __shared__ float red[8][E];
    __shared__ float s2[2];
    const int e = threadIdx.x & 63;
    const int part = threadIdx.x >> 6;
    const int nb = N / TILE_M;
    float s = 0.f;
    for (int bb = part; bb < nb; bb += 8) s += g_partial[bb * E + e];
    red[part][e] = s;
    __syncthreads();
    float val = 0.f;
    if (threadIdx.x < E) {
        s = 0.f;
#pragma unroll
        for (int r = 0; r < 8; r++) s += red[r][e];
        const float pm  = s / (float)N;
        const float cnt = (float)g_cnt[e];
        const float am  = cnt / (float)N;
        out[(size_t)4 * N + 1 + e] = cnt;
        val = pm * pm + am * am;
    }
    val += __shfl_xor_sync(0xffffffffu, val, 16);
    val += __shfl_xor_sync(0xffffffffu, val, 8);
    val += __shfl_xor_sync(0xffffffffu, val, 4);
    val += __shfl_xor_sync(0xffffffffu, val, 2);
    val += __shfl_xor_sync(0xffffffffu, val, 1);
    if ((threadIdx.x & 31) == 0 && threadIdx.x < 64) s2[threadIdx.x >> 5] = val;
    __syncthreads();
    if (threadIdx.x == 0) out[(size_t)4 * N] = (float)E * (s2[0] + s2[1]);
}

extern "C" void kernel_launch(void* const* d_in, const int* in_sizes, int n_in,
                              void* d_out, int out_size) {
    const float* x = (const float*)d_in[0];
    const float* W = (const float*)d_in[1];
    float* out = (float*)d_out;
    const int N = in_sizes[0] / H;  // 16384

    cudaFuncSetAttribute(gemm_kernel, cudaFuncAttributeMaxDynamicSharedMemorySize,
                         SMEM_TOTAL);

    prep_kernel<<<(E * H) / 2048, 256>>>(W);
    gemm_kernel<<<N / TILE_M, NTHREADS, SMEM_TOTAL>>>(x, out, N);
    fixup_kernel<<<MAXFLAG, 256>>>(x, W, out, N);
    finalize_kernel<<<1, 512>>>(out, N);
}

// round 17
// speedup vs baseline: 1.3241x; 1.2362x over previous
#include <cuda_runtime.h>
#include <cuda_bf16.h>
#include <cstdint>

#define H 2048
#define E 64
#define MAXN 16384
#define TILE_M 128
#define KC 64
#define CHUNKS (H / KC)  // 32
#define MAXFLAG 512
#define NTHREADS 384     // 256 consumer + 128 producer
#define DEPTH 3

// ---------------- device scratch ----------------
__device__ __align__(16) __nv_bfloat16 g_Wh[E * H];
__device__ __align__(16) __nv_bfloat16 g_Wl[E * H];
__device__ float g_partial[(MAXN / TILE_M) * E];
__device__ int   g_cnt[E];
__device__ int   g_nflag;
__device__ int   g_flaglist[MAXFLAG];

// ---------------- helpers ----------------
__device__ __forceinline__ uint32_t smem_u32(const void* p) {
    uint32_t a;
    asm("{ .reg .u64 t; cvta.to.shared.u64 t, %1; cvt.u32.u64 %0, t; }" : "=r"(a) : "l"(p));
    return a;
}
__device__ __forceinline__ uint32_t sw128(uint32_t o) { return o ^ ((o >> 3) & 0x70); }

__device__ __forceinline__ void split2(float v, float& h, float& l) {
    h = __bfloat162float(__float2bfloat16_rn(v));
    l = v - h;
}
__device__ __forceinline__ uint32_t packbf(float a, float b) {
    __nv_bfloat162 t = __floats2bfloat162_rn(a, b);
    return *reinterpret_cast<uint32_t*>(&t);
}

#define CP_ASYNC16(dst, src)                                                             \
    asm volatile("cp.async.cg.shared.global [%0], [%1], 16;" :: "r"(dst), "l"(src))
#define CP_COMMIT()  asm volatile("cp.async.commit_group;" ::: "memory")
#define CP_WAIT0()   asm volatile("cp.async.wait_group 0;" ::: "memory")

#define BAR_SYNC(id)   asm volatile("bar.sync %0, %1;" :: "r"(id), "r"(NTHREADS) : "memory")
#define BAR_ARRIVE(id) asm volatile("bar.arrive %0, %1;" :: "r"(id), "r"(NTHREADS) : "memory")

#define LDSM4(r, addr)                                                                   \
    asm volatile("ldmatrix.sync.aligned.m8n8.x4.shared.b16 {%0,%1,%2,%3}, [%4];"         \
        : "=r"((r)[0]), "=r"((r)[1]), "=r"((r)[2]), "=r"((r)[3]) : "r"(addr))

#define MMA16816(ac, a, b0, b1)                                                          \
    asm volatile("mma.sync.aligned.m16n8k16.row.col.f32.bf16.bf16.f32 "                  \
        "{%0,%1,%2,%3}, {%4,%5,%6,%7}, {%8,%9}, {%0,%1,%2,%3};"                          \
        : "+f"((ac)[0]), "+f"((ac)[1]), "+f"((ac)[2]), "+f"((ac)[3])                     \
        : "r"((a)[0]), "r"((a)[1]), "r"((a)[2]), "r"((a)[3]), "r"(b0), "r"(b1))

// ---------------- kernel 0: split W once, zero counters ----------------
__global__ __launch_bounds__(256) void prep_kernel(const float* __restrict__ W) {
    const int i = (blockIdx.x * 256 + threadIdx.x) * 8;
    if (i < E * H) {
        float4 v0 = *(const float4*)(W + i);
        float4 v1 = *(const float4*)(W + i + 4);
        float vv[8] = {v0.x, v0.y, v0.z, v0.w, v1.x, v1.y, v1.z, v1.w};
        uint32_t ph[4], pl[4];
#pragma unroll
        for (int q = 0; q < 4; q++) {
            float h0, l0, h1, l1;
            split2(vv[2 * q], h0, l0);
            split2(vv[2 * q + 1], h1, l1);
            ph[q] = packbf(h0, h1);
            pl[q] = packbf(l0, l1);
        }
        *(uint4*)(g_Wh + i) = make_uint4(ph[0], ph[1], ph[2], ph[3]);
        *(uint4*)(g_Wl + i) = make_uint4(pl[0], pl[1], pl[2], pl[3]);
    }
    if (blockIdx.x == 0 && threadIdx.x < E) g_cnt[threadIdx.x] = 0;
    if (blockIdx.x == 0 && threadIdx.x == 0) g_nflag = 0;
}

// ---------------- kernel 1: warp-specialized split-bf16 HMMA GEMM, depth-3 ----------------
// Stage (48KB): A_hi@0 (16K) A_lo@16K B_hi@32K B_lo@40K. 3 stages = 144KB.
static constexpr int A_SZ   = 16384;
static constexpr int B_SZ   = 8192;
static constexpr int B_OFFS = 2 * A_SZ;             // 32768
static constexpr int STG_SZ = B_OFFS + 2 * B_SZ;    // 49152
static constexpr int OFF_SP = DEPTH * STG_SZ;       // 147456
static constexpr int SMEM_TOTAL = OFF_SP + 4 * E * 4;  // 148480

// named barriers: ready[s] = 1+s, free[s] = 4+s  (s in {0,1,2})
__global__ __launch_bounds__(NTHREADS, 1) void gemm_kernel(const float* __restrict__ x,
                                                           float* __restrict__ out, int N) {
    extern __shared__ char sdata[];
    const uint32_t sb = smem_u32(sdata);
    const int tid = threadIdx.x;
    const int wid = tid >> 5, lid = tid & 31;
    const int row0 = blockIdx.x * TILE_M;

    float acc[8][4] = {};

    if (tid >= 256) {
        // ================= PRODUCER (warps 8-11, 128 threads) =================
        const int tp = tid - 256;           // 0..127
        const int pw = tp >> 5;             // producer warp 0..3
        const int pl_ = tp & 31;
        // coalesced A map: 8 threads/row, 32B (8 floats) per thread
        const int rowin = pw * 4 + (pl_ >> 3);  // row-within-pass 0..15
        const int tcol = pl_ & 7;               // 8-float column chunk
        // B map (cp.async): 2 threads/row
        const int rB = tp >> 1;
        const int cB = (tp & 1) * 4;
        const size_t wrow = (size_t)rB * H;

        for (int c = 0; c < CHUNKS; c++) {
            const int s = c % DEPTH;
            if (c >= DEPTH) BAR_SYNC(4 + s);
            const uint32_t stg = sb + s * STG_SZ;
            char* stgp = sdata + s * STG_SZ;
            const int k0 = c * KC;

            // B tiles via cp.async
#pragma unroll
            for (int q = 0; q < 4; q++) {
                const uint32_t dst = sw128((uint32_t)(rB * 128 + (cB + q) * 16));
                const size_t srcoff = wrow + k0 + (cB + q) * 8;
                CP_ASYNC16(stg + B_OFFS + dst, g_Wh + srcoff);
                CP_ASYNC16(stg + B_OFFS + B_SZ + dst, g_Wl + srcoff);
            }
            CP_COMMIT();

            // A: 8 passes x 16 rows, coalesced 32B/thread
#pragma unroll
            for (int i = 0; i < 8; i++) {
                const int row = i * 16 + rowin;
                const float4* xp = (const float4*)(x + (size_t)(row0 + row) * H + k0);
                float4 a0 = xp[tcol * 2];
                float4 a1 = xp[tcol * 2 + 1];
                float v[8] = {a0.x, a0.y, a0.z, a0.w, a1.x, a1.y, a1.z, a1.w};
                uint32_t ph[4], pl2[4];
#pragma unroll
                for (int q = 0; q < 4; q++) {
                    float h0, l0, h1, l1;
                    split2(v[2 * q], h0, l0);
                    split2(v[2 * q + 1], h1, l1);
                    ph[q] = packbf(h0, h1); pl2[q] = packbf(l0, l1);
                }
                const uint32_t off = sw128((uint32_t)(row * 128 + tcol * 16));
                *(uint4*)(stgp + off)        = make_uint4(ph[0], ph[1], ph[2], ph[3]);
                *(uint4*)(stgp + A_SZ + off) = make_uint4(pl2[0], pl2[1], pl2[2], pl2[3]);
            }
            CP_WAIT0();
            BAR_ARRIVE(1 + s);
        }
    } else {
        // ================= CONSUMER (warps 0-7, 256 threads) =================
        const int idx = lid >> 3;
        const int a_row = wid * 16 + (idx & 1) * 8 + (lid & 7);
        const uint32_t a_rowbyte = (uint32_t)a_row * 128;
        const uint32_t a_xor = (uint32_t)(a_row & 7) << 4;
        const uint32_t a_k2 = (uint32_t)(idx >> 1) * 16;
        const int b_n0 = (idx >> 1) * 8 + (lid & 7);
        const uint32_t b_k2 = (uint32_t)(idx & 1) * 16;
        uint32_t b_rowbyte[4], b_xor[4];
#pragma unroll
        for (int j = 0; j < 4; j++) {
            int nr = j * 16 + b_n0;
            b_rowbyte[j] = (uint32_t)nr * 128;
            b_xor[j] = (uint32_t)(nr & 7) << 4;
        }

        for (int c = 0; c < CHUNKS; c++) {
            const int s = c % DEPTH;
            BAR_SYNC(1 + s);
            const uint32_t sbuf = sb + s * STG_SZ;
#pragma unroll
            for (int ks = 0; ks < 4; ks++) {
                const uint32_t kcol = (uint32_t)ks * 32;
                uint32_t Af[2][4], Bh[4][4], Bl[4][4];
                LDSM4(Af[0], sbuf + a_rowbyte + ((kcol + a_k2) ^ a_xor));
                LDSM4(Af[1], sbuf + A_SZ + a_rowbyte + ((kcol + a_k2) ^ a_xor));
#pragma unroll
                for (int j = 0; j < 4; j++)
                    LDSM4(Bh[j], sbuf + B_OFFS + b_rowbyte[j] + ((kcol + b_k2) ^ b_xor[j]));
#pragma unroll
                for (int j = 0; j < 4; j++) {
                    MMA16816(acc[2 * j],     Af[0], Bh[j][0], Bh[j][1]);
                    MMA16816(acc[2 * j + 1], Af[0], Bh[j][2], Bh[j][3]);
                }
#pragma unroll
                for (int j = 0; j < 4; j++)
                    LDSM4(Bl[j], sbuf + B_OFFS + B_SZ + b_rowbyte[j] + ((kcol + b_k2) ^ b_xor[j]));
#pragma unroll
                for (int j = 0; j < 4; j++) {
                    MMA16816(acc[2 * j],     Af[1], Bh[j][0], Bh[j][1]);
                    MMA16816(acc[2 * j + 1], Af[1], Bh[j][2], Bh[j][3]);
                }
#pragma unroll
                for (int j = 0; j < 4; j++) {
                    MMA16816(acc[2 * j],     Af[0], Bl[j][0], Bl[j][1]);
                    MMA16816(acc[2 * j + 1], Af[0], Bl[j][2], Bl[j][3]);
                }
            }
            BAR_ARRIVE(4 + s);
        }
    }

    __syncthreads();  // all MMAs + producers done

    // ---- C frags -> smem logits (overlay stage 0) ----
    float* lg = (float*)sdata;
    if (tid < 256) {
        const int r0f = wid * 16 + (lid >> 2);
        const int c0f = (lid & 3) * 2;
#pragma unroll
        for (int nt = 0; nt < 8; nt++) {
            int col = nt * 8 + c0f;
            lg[r0f * 65 + col]           = acc[nt][0];
            lg[r0f * 65 + col + 1]       = acc[nt][1];
            lg[(r0f + 8) * 65 + col]     = acc[nt][2];
            lg[(r0f + 8) * 65 + col + 1] = acc[nt][3];
        }
    }
    __syncthreads();

    // ---- per-token softmax / top-2 / near-tie flag / reductions ----
    float* s_part = (float*)(sdata + OFF_SP);  // [4][64]
    if (tid < 128) {
        float p[E];
#pragma unroll
        for (int e = 0; e < E; e++) p[e] = lg[tid * 65 + e];

        float mx = p[0];
#pragma unroll
        for (int e = 1; e < E; e++) mx = fmaxf(mx, p[e]);
        float denom = 0.f;
#pragma unroll
        for (int e = 0; e < E; e++) { p[e] = __expf(p[e] - mx); denom += p[e]; }
        const float inv = 1.f / denom;
#pragma unroll
        for (int e = 0; e < E; e++) p[e] *= inv;

        float m1 = -1.f, m2 = -1.f, m3 = -1.f;
        int i1 = 0, i2 = 0;
#pragma unroll
        for (int e = 0; e < E; e++) {
            float v = p[e];
            if (v > m1)      { m3 = m2; m2 = m1; i2 = i1; m1 = v; i1 = e; }
            else if (v > m2) { m3 = m2; m2 = v; i2 = e; }
            else if (v > m3) { m3 = v; }
        }
        const int token = row0 + tid;
        const float d = m1 + m2 + 1e-6f;
        out[(size_t)token * 2 + 0] = m1 / d;
        out[(size_t)token * 2 + 1] = m2 / d;
        float* oidx = out + (size_t)2 * N;
        oidx[(size_t)token * 2 + 0] = (float)i1;
        oidx[(size_t)token * 2 + 1] = (float)i2;

        atomicAdd(&g_cnt[i1], 1);
        atomicAdd(&g_cnt[i2], 1);

        if ((m1 - m2 < 6e-5f * m1) || (m2 - m3 < 6e-5f * m2)) {
            int s = atomicAdd(&g_nflag, 1);
            if (s < MAXFLAG) g_flaglist[s] = token;
        }

#pragma unroll
        for (int e = 0; e < E; e++) {
            float v = p[e];
            v += __shfl_xor_sync(0xffffffffu, v, 16);
            v += __shfl_xor_sync(0xffffffffu, v, 8);
            v += __shfl_xor_sync(0xffffffffu, v, 4);
            v += __shfl_xor_sync(0xffffffffu, v, 2);
            v += __shfl_xor_sync(0xffffffffu, v, 1);
            if (lid == 0) s_part[wid * E + e] = v;
        }
    }
    __syncthreads();
    if (tid < E) {
        float s = s_part[tid] + s_part[E + tid] + s_part[2 * E + tid] + s_part[3 * E + tid];
        g_partial[blockIdx.x * E + tid] = s;
    }
}

// ---------------- kernel 2: exact fp32 fixup (1 block per flagged token) ----------------
__global__ __launch_bounds__(256) void fixup_kernel(const float* __restrict__ x,
                                                    const float* __restrict__ W,
                                                    float* __restrict__ out, int N) {
    int n = g_nflag;
    if (n > MAXFLAG) n = MAXFLAG;
    if (blockIdx.x >= n) return;
    const int token = g_flaglist[blockIdx.x];

    __shared__ float sq[4][E];
    __shared__ float sl[E];
    const int e = threadIdx.x & 63;
    const int q = threadIdx.x >> 6;

    const float* xr = x + (size_t)token * H + q * (H / 4);
    const float* wr = W + (size_t)e * H + q * (H / 4);
    float a = 0.f;
#pragma unroll 4
    for (int h = 0; h < H / 4; h += 4) {
        float4 xv = *(const float4*)(xr + h);
        float4 wv = *(const float4*)(wr + h);
        a += xv.x * wv.x + xv.y * wv.y + xv.z * wv.z + xv.w * wv.w;
    }
    sq[q][e] = a;
    __syncthreads();
    if (threadIdx.x < E) sl[threadIdx.x] = sq[0][threadIdx.x] + sq[1][threadIdx.x]
                                         + sq[2][threadIdx.x] + sq[3][threadIdx.x];
    __syncthreads();
    if (threadIdx.x == 0) {
        float mx = sl[0];
        for (int i = 1; i < E; i++) mx = fmaxf(mx, sl[i]);
        float Z = 0.f;
        for (int i = 0; i < E; i++) Z += __expf(sl[i] - mx);
        float m1 = -1e30f, m2 = -1e30f;
        int i1 = 0, i2 = 0;
        for (int i = 0; i < E; i++) {
            float v = sl[i];
            if (v > m1)      { m2 = m1; i2 = i1; m1 = v; i1 = i; }
            else if (v > m2) { m2 = v; i2 = i; }
        }
        float p1 = __expf(m1 - mx) / Z;
        float p2 = __expf(m2 - mx) / Z;
        float d = p1 + p2 + 1e-6f;
        float* oidx = out + (size_t)2 * N;
        int o1 = (int)oidx[(size_t)token * 2 + 0];
        int o2 = (int)oidx[(size_t)token * 2 + 1];
        out[(size_t)token * 2 + 0] = p1 / d;
        out[(size_t)token * 2 + 1] = p2 / d;
        oidx[(size_t)token * 2 + 0] = (float)i1;
        oidx[(size_t)token * 2 + 1] = (float)i2;
        atomicAdd(&g_cnt[o1], -1);
        atomicAdd(&g_cnt[o2], -1);
        atomicAdd(&g_cnt[i1], 1);
        atomicAdd(&g_cnt[i2], 1);
    }
}

// ---------------- kernel 3: aux loss + counts ----------------
__global__ __launch_bounds__(512) void finalize_kernel(float* __restrict__ out, int N) {
    __shared__ float red[8][E];
    __shared__ float s2[2];
    const int e = threadIdx.x & 63;
    const int part = threadIdx.x >> 6;
    const int nb = N / TILE_M;
    float s = 0.f;
    for (int bb = part; bb < nb; bb += 8) s += g_partial[bb * E + e];
    red[part][e] = s;
    __syncthreads();
    float val = 0.f;
    if (threadIdx.x < E) {
        s = 0.f;
#pragma unroll
        for (int r = 0; r < 8; r++) s += red[r][e];
        const float pm  = s / (float)N;
        const float cnt = (float)g_cnt[e];
        const float am  = cnt / (float)N;
        out[(size_t)4 * N + 1 + e] = cnt;
        val = pm * pm + am * am;
    }
    val += __shfl_xor_sync(0xffffffffu, val, 16);
    val += __shfl_xor_sync(0xffffffffu, val, 8);
    val += __shfl_xor_sync(0xffffffffu, val, 4);
    val += __shfl_xor_sync(0xffffffffu, val, 2);
    val += __shfl_xor_sync(0xffffffffu, val, 1);
    if ((threadIdx.x & 31) == 0 && threadIdx.x < 64) s2[threadIdx.x >> 5] = val;
    __syncthreads();
    if (threadIdx.x == 0) out[(size_t)4 * N] = (float)E * (s2[0] + s2[1]);
}

extern "C" void kernel_launch(void* const* d_in, const int* in_sizes, int n_in,
                              void* d_out, int out_size) {
    const float* x = (const float*)d_in[0];
    const float* W = (const float*)d_in[1];
    float* out = (float*)d_out;
    const int N = in_sizes[0] / H;  // 16384

    cudaFuncSetAttribute(gemm_kernel, cudaFuncAttributeMaxDynamicSharedMemorySize,
                         SMEM_TOTAL);

    prep_kernel<<<(E * H) / 2048, 256>>>(W);
    gemm_kernel<<<N / TILE_M, NTHREADS, SMEM_TOTAL>>>(x, out, N);
    fixup_kernel<<<MAXFLAG, 256>>>(x, W, out, N);
    finalize_kernel<<<1, 512>>>(out, N);
}